// round 15
// baseline (speedup 1.0000x reference)
#include <cuda_runtime.h>
#include <cuda_fp16.h>

typedef unsigned int u32;
typedef unsigned long long u64;

#define NBLK  128
#define NTHR  256
#define ROWS  64
#define HPAD  132
#define NSTEP 49

// ---- dynamic smem layout (float offsets) ----
#define F_XPS   0        // 64
#define F_WIHS  64       // 384
#define F_BIHS  448      // 384
#define F_BHHS  832      // 384
#define F_DW1   1216     // 16
#define F_DB0   1232     // 16
#define F_DB1   1248     // 1 (pad to 1280)
#define F_DFRAG 1280     // 256 uint4 = 1024 floats
#define F_T0    2304     // fp16 tile [64][136] = 4352 floats
#define F_T1    6656     // 4352
#define F_HS    11008    // 32*256 hold slots = 8192
#define F_HA    19200    // encoder scratch 64*132 = 8448
#define SMEM_FLOATS 27648
#define SMEM_BYTES  (SMEM_FLOATS*4)

// GRU A fragments (fp16 weights): [g][wm][k][lane] as uint4
__device__ uint4 g_wfrag[3 * 8 * 8 * 32];
// decoder A fragments (fp16): [k][lane] as uint4 (m16 x k128)
__device__ uint4 g_dfrag[8 * 32];

#define MMA(c, a, b0v, b1v) asm volatile( \
    "mma.sync.aligned.m16n8k16.row.col.f32.f16.f16.f32 " \
    "{%0,%1,%2,%3}, {%4,%5,%6,%7}, {%8,%9}, {%0,%1,%2,%3};" \
    : "+f"((c)[0]), "+f"((c)[1]), "+f"((c)[2]), "+f"((c)[3]) \
    : "r"((a).x), "r"((a).y), "r"((a).z), "r"((a).w), "r"(b0v), "r"(b1v))

__device__ __forceinline__ float tanha(float x) {
    float y;
    asm("tanh.approx.f32 %0, %1;" : "=f"(y) : "f"(x));
    return y;
}
__device__ __forceinline__ float sigm(float x) {
    return fmaf(0.5f, tanha(0.5f * x), 0.5f);
}
__device__ __forceinline__ u32 pack_h2(__half lo, __half hi) {
    return ((u32)__half_as_ushort(hi) << 16) | (u32)__half_as_ushort(lo);
}

// ---------------- weight repack (fp16) ----------------
__global__ void repack(const float* __restrict__ whh, const float* __restrict__ dw0) {
    int idx = blockIdx.x * blockDim.x + threadIdx.x;
    if (idx < 6144) {
        int lane = idx & 31;
        int k    = (idx >> 5) & 7;
        int wm   = (idx >> 8) & 7;
        int g    = idx >> 11;          // 0..2
        int row  = g * 128 + wm * 16 + (lane >> 2);
        int k0   = k * 16 + (lane & 3) * 2;
        u32 o[4];
        #pragma unroll
        for (int q = 0; q < 4; ++q) {
            int rr = row + 8 * (q & 1);
            int kk = k0 + 8 * (q >> 1);
            o[q] = pack_h2(__float2half(whh[rr * 128 + kk]),
                           __float2half(whh[rr * 128 + kk + 1]));
        }
        g_wfrag[idx] = make_uint4(o[0], o[1], o[2], o[3]);
    } else if (idx < 6400) {
        int local = idx - 6144;
        int lane = local & 31;
        int k    = local >> 5;         // 0..7
        int row  = lane >> 2;
        int k0   = k * 16 + (lane & 3) * 2;
        u32 o[4];
        #pragma unroll
        for (int q = 0; q < 4; ++q) {
            int rr = row + 8 * (q & 1);
            int kk = k0 + 8 * (q >> 1);
            o[q] = pack_h2(__float2half(dw0[kk * 16 + rr]),
                           __float2half(dw0[(kk + 1) * 16 + rr]));
        }
        g_dfrag[local] = make_uint4(o[0], o[1], o[2], o[3]);
    }
}

// one 128->128 encoder layer (reads/writes ha), scalar fp32, 256 threads
// thread: p = tid&15 -> rows {p, p+16, p+32, p+48}; t = tid>>4 -> units [t*8, t*8+8)
__device__ __forceinline__ void enc_layer128(const float* __restrict__ w,
                                             const float* __restrict__ b,
                                             float* ha, int p, int t, bool relu_on) {
    float acc[8][4];
    #pragma unroll
    for (int uu = 0; uu < 8; ++uu)
        #pragma unroll
        for (int m = 0; m < 4; ++m) acc[uu][m] = 0.0f;
    const float4* w4 = (const float4*)w;
    for (int k4 = 0; k4 < 32; ++k4) {
        float xa[4][4];
        #pragma unroll
        for (int m = 0; m < 4; ++m) {
            float4 v = *(const float4*)&ha[(p + 16*m)*HPAD + k4*4];
            xa[m][0] = v.x; xa[m][1] = v.y; xa[m][2] = v.z; xa[m][3] = v.w;
        }
        #pragma unroll
        for (int kk = 0; kk < 4; ++kk) {
            #pragma unroll
            for (int ub = 0; ub < 2; ++ub) {
                float4 wv = __ldg(&w4[(k4*4 + kk)*32 + t*2 + ub]);
                #pragma unroll
                for (int m = 0; m < 4; ++m) {
                    acc[ub*4+0][m] = fmaf(wv.x, xa[m][kk], acc[ub*4+0][m]);
                    acc[ub*4+1][m] = fmaf(wv.y, xa[m][kk], acc[ub*4+1][m]);
                    acc[ub*4+2][m] = fmaf(wv.z, xa[m][kk], acc[ub*4+2][m]);
                    acc[ub*4+3][m] = fmaf(wv.w, xa[m][kk], acc[ub*4+3][m]);
                }
            }
        }
    }
    __syncthreads();
    #pragma unroll
    for (int uu = 0; uu < 8; ++uu) {
        int u = t*8 + uu;
        float bv = __ldg(&b[u]);
        #pragma unroll
        for (int m = 0; m < 4; ++m) {
            float v = acc[uu][m] + bv;
            ha[(p + 16*m)*HPAD + u] = relu_on ? fmaxf(v, 0.0f) : v;
        }
    }
    __syncthreads();
}

__global__ void __launch_bounds__(NTHR, 1)
gru_kernel(const float* __restrict__ x,
           const float* __restrict__ ew0, const float* __restrict__ eb0,
           const float* __restrict__ ew1, const float* __restrict__ eb1,
           const float* __restrict__ ew2, const float* __restrict__ eb2,
           const float* __restrict__ wih, const float* __restrict__ whh,
           const float* __restrict__ bih, const float* __restrict__ bhh,
           const float* __restrict__ dw0, const float* __restrict__ db0,
           const float* __restrict__ dw1, const float* __restrict__ db1,
           float* __restrict__ out) {
    extern __shared__ float sm[];
    float* xps  = sm + F_XPS;
    float* wihs = sm + F_WIHS;
    float* bihs = sm + F_BIHS;
    float* bhhs = sm + F_BHHS;
    float* dw1s = sm + F_DW1;
    float* db0s = sm + F_DB0;
    uint4* dsm4 = (uint4*)(sm + F_DFRAG);
    char*  t0   = (char*)(sm + F_T0);
    char*  t1   = (char*)(sm + F_T1);
    float* hsm  = sm + F_HS;
    float* ha   = sm + F_HA;

    const int tid  = threadIdx.x;
    const int wid  = tid >> 5;      // 0..7: unit block [wid*16, wid*16+16)
    const int lane = tid & 31;
    const int qrow = lane >> 2;     // 0..7
    const int qcol = lane & 3;      // 0..3
    const int row0 = blockIdx.x * ROWS;

    // ---- small smem init ----
    for (int j = tid; j < 384; j += NTHR) {
        wihs[j] = wih[j]; bihs[j] = bih[j]; bhhs[j] = bhh[j];
    }
    for (int j = tid; j < 256; j += NTHR) dsm4[j] = __ldg(&g_dfrag[j]);
    if (tid < 16) { dw1s[tid] = dw1[tid]; db0s[tid] = db0[tid]; }
    if (tid == 0) sm[F_DB1] = db1[0];
    if (tid < ROWS) {
        xps[tid] = 0.0f;
        out[(u64)(row0 + tid)*50] = 0.0f;
    }

    // ---- encoder (scalar fp32, 256 threads) ----
    {
        const int p = tid & 15, t = tid >> 4;
        float acc[8][4];
        #pragma unroll
        for (int uu = 0; uu < 8; ++uu)
            #pragma unroll
            for (int m = 0; m < 4; ++m) acc[uu][m] = 0.0f;
        const float4* x4  = (const float4*)x;
        const float4* w04 = (const float4*)ew0;
        for (int k4 = 0; k4 < 64; ++k4) {
            float xa[4][4];
            #pragma unroll
            for (int m = 0; m < 4; ++m) {
                float4 v = __ldg(&x4[(u64)(row0 + p + 16*m)*64 + k4]);
                xa[m][0] = v.x; xa[m][1] = v.y; xa[m][2] = v.z; xa[m][3] = v.w;
            }
            #pragma unroll
            for (int kk = 0; kk < 4; ++kk) {
                #pragma unroll
                for (int ub = 0; ub < 2; ++ub) {
                    float4 wv = __ldg(&w04[(k4*4 + kk)*32 + t*2 + ub]);
                    #pragma unroll
                    for (int m = 0; m < 4; ++m) {
                        acc[ub*4+0][m] = fmaf(wv.x, xa[m][kk], acc[ub*4+0][m]);
                        acc[ub*4+1][m] = fmaf(wv.y, xa[m][kk], acc[ub*4+1][m]);
                        acc[ub*4+2][m] = fmaf(wv.z, xa[m][kk], acc[ub*4+2][m]);
                        acc[ub*4+3][m] = fmaf(wv.w, xa[m][kk], acc[ub*4+3][m]);
                    }
                }
            }
        }
        __syncthreads();
        #pragma unroll
        for (int uu = 0; uu < 8; ++uu) {
            int u = t*8 + uu;
            float bv = __ldg(&eb0[u]);
            #pragma unroll
            for (int m = 0; m < 4; ++m)
                ha[(p + 16*m)*HPAD + u] = fmaxf(acc[uu][m] + bv, 0.0f);
        }
        __syncthreads();
        enc_layer128(ew1, eb1, ha, p, tid >> 4, true);
        enc_layer128(ew2, eb2, ha, p, tid >> 4, false);
    }

    // ---- h0: ha -> fp16 tile0 + hold slots ----
    for (int j = tid; j < 8192; j += NTHR) {
        int r = j >> 7, u = j & 127;
        *(__half*)(t0 + r*272 + u*2) = __float2half(ha[r*HPAD + u]);
    }
    #pragma unroll
    for (int nt = 0; nt < 8; ++nt)
        #pragma unroll
        for (int i = 0; i < 2; ++i)
            #pragma unroll
            for (int j = 0; j < 2; ++j) {
                int u = wid*16 + qrow + 8*i;
                int r = nt*8 + qcol*2 + j;
                hsm[(nt*4 + i*2 + j)*NTHR + tid] = ha[r*HPAD + u];
            }
    __syncthreads();

    // ---- register-resident GRU weights (persist across all 49 steps) ----
    uint4 wreg[3][8];
    #pragma unroll
    for (int g = 0; g < 3; ++g)
        #pragma unroll
        for (int k = 0; k < 8; ++k)
            wreg[g][k] = __ldg(&g_wfrag[(g*8 + wid)*256 + k*32 + lane]);

    // ---- hoisted gate constants (2 unit slots per thread) ----
    float wirr[2], wizr[2], winr[2], brr[2], bzr[2], bnir[2], bnhr[2];
    #pragma unroll
    for (int i = 0; i < 2; ++i) {
        int u = wid*16 + qrow + 8*i;
        wirr[i] = wihs[u]; wizr[i] = wihs[128 + u]; winr[i] = wihs[256 + u];
        brr[i]  = bihs[u] + bhhs[u];
        bzr[i]  = bihs[128 + u] + bhhs[128 + u];
        bnir[i] = bihs[256 + u];
        bnhr[i] = bhhs[256 + u];
    }
    const float db1v = sm[F_DB1];

    // ---- GRU + decoder, 49 steps ----
    for (int s = 0; s < NSTEP; ++s) {
        const char* tin = (s & 1) ? t1 : t0;
        char* tout      = (s & 1) ? t0 : t1;

        #pragma unroll
        for (int nt = 0; nt < 8; ++nt) {
            float acc[3][4];
            #pragma unroll
            for (int g = 0; g < 3; ++g)
                #pragma unroll
                for (int q = 0; q < 4; ++q) acc[g][q] = 0.0f;

            #pragma unroll
            for (int k = 0; k < 8; ++k) {
                int off = (nt*8 + qrow)*272 + k*32 + qcol*4;
                u32 b0 = *(const u32*)(tin + off);
                u32 b1 = *(const u32*)(tin + off + 16);
                MMA(acc[0], wreg[0][k], b0, b1);
                MMA(acc[1], wreg[1][k], b0, b1);
                MMA(acc[2], wreg[2][k], b0, b1);
            }

            #pragma unroll
            for (int i = 0; i < 2; ++i) {
                int u = wid*16 + qrow + 8*i;
                #pragma unroll
                for (int j = 0; j < 2; ++j) {
                    int q = 2*i + j;
                    int r = nt*8 + qcol*2 + j;
                    int slot = (nt*4 + i*2 + j)*NTHR + tid;
                    float xp   = xps[r];
                    float hold = hsm[slot];
                    float rg = sigm(acc[0][q] + fmaf(xp, wirr[i], brr[i]));
                    float zg = sigm(acc[1][q] + fmaf(xp, wizr[i], bzr[i]));
                    float ng = tanha(fmaf(xp, winr[i], bnir[i]) + rg*(acc[2][q] + bnhr[i]));
                    float h  = (1.0f - zg)*ng + zg*hold;
                    hsm[slot] = h;
                    *(__half*)(tout + r*272 + u*2) = __float2half(h);
                }
            }
        }
        __syncthreads();   // h_{s+1} tile complete

        // ---- decoder on tout -> out col s+1, xps = x_{s+1} ----
        {
            float dacc[4] = {0.0f, 0.0f, 0.0f, 0.0f};
            #pragma unroll
            for (int k = 0; k < 8; ++k) {
                int off = (wid*8 + qrow)*272 + k*32 + qcol*4;
                u32 b0 = *(const u32*)(tout + off);
                u32 b1 = *(const u32*)(tout + off + 16);
                uint4 ah = dsm4[k*32 + lane];
                MMA(dacc, ah, b0, b1);
            }
            int i = qrow;
            float w1a = dw1s[i], w1b = dw1s[i + 8];
            float b0a = db0s[i], b0b = db0s[i + 8];
            float v0 = fmaxf(dacc[0] + b0a, 0.0f)*w1a + fmaxf(dacc[2] + b0b, 0.0f)*w1b;
            float v1 = fmaxf(dacc[1] + b0a, 0.0f)*w1a + fmaxf(dacc[3] + b0b, 0.0f)*w1b;
            v0 += __shfl_xor_sync(0xffffffffu, v0, 4);
            v0 += __shfl_xor_sync(0xffffffffu, v0, 8);
            v0 += __shfl_xor_sync(0xffffffffu, v0, 16);
            v1 += __shfl_xor_sync(0xffffffffu, v1, 4);
            v1 += __shfl_xor_sync(0xffffffffu, v1, 8);
            v1 += __shfl_xor_sync(0xffffffffu, v1, 16);
            if (lane < 4) {
                int r0 = wid*8 + lane*2;
                float o0 = v0 + db1v;
                float o1 = v1 + db1v;
                out[(u64)(row0 + r0)*50 + s + 1] = o0;
                out[(u64)(row0 + r0 + 1)*50 + s + 1] = o1;
                xps[r0]     = o0;
                xps[r0 + 1] = o1;
            }
        }
        __syncthreads();   // xps ready for next step
    }
}

extern "C" void kernel_launch(void* const* d_in, const int* in_sizes, int n_in,
                              void* d_out, int out_size) {
    (void)in_sizes; (void)n_in; (void)out_size;
    const float* x   = (const float*)d_in[0];
    const float* ew0 = (const float*)d_in[1];
    const float* eb0 = (const float*)d_in[2];
    const float* ew1 = (const float*)d_in[3];
    const float* eb1 = (const float*)d_in[4];
    const float* ew2 = (const float*)d_in[5];
    const float* eb2 = (const float*)d_in[6];
    const float* wih = (const float*)d_in[7];
    const float* whh = (const float*)d_in[8];
    const float* bih = (const float*)d_in[9];
    const float* bhh = (const float*)d_in[10];
    const float* dw0 = (const float*)d_in[11];
    const float* db0 = (const float*)d_in[12];
    const float* dw1 = (const float*)d_in[13];
    const float* db1 = (const float*)d_in[14];
    float* out = (float*)d_out;

    cudaFuncSetAttribute(gru_kernel, cudaFuncAttributeMaxDynamicSharedMemorySize, SMEM_BYTES);

    repack<<<13, 512>>>(whh, dw0);
    gru_kernel<<<NBLK, NTHR, SMEM_BYTES>>>(x, ew0, eb0, ew1, eb1, ew2, eb2,
                                           wih, whh, bih, bhh, dw0, db0, dw1, db1, out);
}

// round 16
// speedup vs baseline: 1.0914x; 1.0914x over previous
#include <cuda_runtime.h>
#include <cuda_fp16.h>

typedef unsigned int u32;
typedef unsigned long long u64;

#define NBLK  256
#define NTHR  256
#define ROWS  32
#define HPAD  132
#define NSTEP 49

// ---- dynamic smem layout (float offsets) ----
#define F_XPS   0        // 32
#define F_WIHS  32       // 384
#define F_BIHS  416      // 384
#define F_BHHS  800      // 384
#define F_DW1   1184     // 16
#define F_DB0   1200     // 16
#define F_DB1   1216     // 1 (pad to 1280)
#define F_DFRAG 1280     // 256 uint4 = 1024 floats
#define F_T0    2304     // fp16 tile [32][136] = 2176 floats
#define F_T1    4480     // 2176
#define F_HS    6656     // 16*256 hold slots = 4096
#define F_HA    10752    // encoder scratch 32*132 = 4224
#define SMEM_FLOATS 14976
#define SMEM_BYTES  (SMEM_FLOATS*4)

// GRU A fragments (fp16 weights): [g][wm][k][lane] as uint4
__device__ uint4 g_wfrag[3 * 8 * 8 * 32];
// decoder A fragments (fp16): [k][lane] as uint4 (m16 x k128)
__device__ uint4 g_dfrag[8 * 32];

#define MMA(c, a, b0v, b1v) asm volatile( \
    "mma.sync.aligned.m16n8k16.row.col.f32.f16.f16.f32 " \
    "{%0,%1,%2,%3}, {%4,%5,%6,%7}, {%8,%9}, {%0,%1,%2,%3};" \
    : "+f"((c)[0]), "+f"((c)[1]), "+f"((c)[2]), "+f"((c)[3]) \
    : "r"((a).x), "r"((a).y), "r"((a).z), "r"((a).w), "r"(b0v), "r"(b1v))

__device__ __forceinline__ float tanha(float x) {
    float y;
    asm("tanh.approx.f32 %0, %1;" : "=f"(y) : "f"(x));
    return y;
}
__device__ __forceinline__ float sigm(float x) {
    return fmaf(0.5f, tanha(0.5f * x), 0.5f);
}
__device__ __forceinline__ u32 pack_h2(__half lo, __half hi) {
    return ((u32)__half_as_ushort(hi) << 16) | (u32)__half_as_ushort(lo);
}

// ---------------- weight repack (fp16) ----------------
__global__ void repack(const float* __restrict__ whh, const float* __restrict__ dw0) {
    int idx = blockIdx.x * blockDim.x + threadIdx.x;
    if (idx < 6144) {
        int lane = idx & 31;
        int k    = (idx >> 5) & 7;
        int wm   = (idx >> 8) & 7;
        int g    = idx >> 11;          // 0..2
        int row  = g * 128 + wm * 16 + (lane >> 2);
        int k0   = k * 16 + (lane & 3) * 2;
        u32 o[4];
        #pragma unroll
        for (int q = 0; q < 4; ++q) {
            int rr = row + 8 * (q & 1);
            int kk = k0 + 8 * (q >> 1);
            o[q] = pack_h2(__float2half(whh[rr * 128 + kk]),
                           __float2half(whh[rr * 128 + kk + 1]));
        }
        g_wfrag[idx] = make_uint4(o[0], o[1], o[2], o[3]);
    } else if (idx < 6400) {
        int local = idx - 6144;
        int lane = local & 31;
        int k    = local >> 5;         // 0..7
        int row  = lane >> 2;
        int k0   = k * 16 + (lane & 3) * 2;
        u32 o[4];
        #pragma unroll
        for (int q = 0; q < 4; ++q) {
            int rr = row + 8 * (q & 1);
            int kk = k0 + 8 * (q >> 1);
            o[q] = pack_h2(__float2half(dw0[kk * 16 + rr]),
                           __float2half(dw0[(kk + 1) * 16 + rr]));
        }
        g_dfrag[local] = make_uint4(o[0], o[1], o[2], o[3]);
    }
}

// one 128->128 encoder layer (reads/writes ha), scalar fp32, 256 threads, 32 rows
// thread: p = tid&15 -> rows {p, p+16}; t = tid>>4 -> units [t*8, t*8+8)
__device__ __forceinline__ void enc_layer128(const float* __restrict__ w,
                                             const float* __restrict__ b,
                                             float* ha, int p, int t, bool relu_on) {
    float acc[8][2];
    #pragma unroll
    for (int uu = 0; uu < 8; ++uu)
        #pragma unroll
        for (int m = 0; m < 2; ++m) acc[uu][m] = 0.0f;
    const float4* w4 = (const float4*)w;
    for (int k4 = 0; k4 < 32; ++k4) {
        float xa[2][4];
        #pragma unroll
        for (int m = 0; m < 2; ++m) {
            float4 v = *(const float4*)&ha[(p + 16*m)*HPAD + k4*4];
            xa[m][0] = v.x; xa[m][1] = v.y; xa[m][2] = v.z; xa[m][3] = v.w;
        }
        #pragma unroll
        for (int kk = 0; kk < 4; ++kk) {
            #pragma unroll
            for (int ub = 0; ub < 2; ++ub) {
                float4 wv = __ldg(&w4[(k4*4 + kk)*32 + t*2 + ub]);
                #pragma unroll
                for (int m = 0; m < 2; ++m) {
                    acc[ub*4+0][m] = fmaf(wv.x, xa[m][kk], acc[ub*4+0][m]);
                    acc[ub*4+1][m] = fmaf(wv.y, xa[m][kk], acc[ub*4+1][m]);
                    acc[ub*4+2][m] = fmaf(wv.z, xa[m][kk], acc[ub*4+2][m]);
                    acc[ub*4+3][m] = fmaf(wv.w, xa[m][kk], acc[ub*4+3][m]);
                }
            }
        }
    }
    __syncthreads();
    #pragma unroll
    for (int uu = 0; uu < 8; ++uu) {
        int u = t*8 + uu;
        float bv = __ldg(&b[u]);
        #pragma unroll
        for (int m = 0; m < 2; ++m) {
            float v = acc[uu][m] + bv;
            ha[(p + 16*m)*HPAD + u] = relu_on ? fmaxf(v, 0.0f) : v;
        }
    }
    __syncthreads();
}

__global__ void __launch_bounds__(NTHR, 2)
gru_kernel(const float* __restrict__ x,
           const float* __restrict__ ew0, const float* __restrict__ eb0,
           const float* __restrict__ ew1, const float* __restrict__ eb1,
           const float* __restrict__ ew2, const float* __restrict__ eb2,
           const float* __restrict__ wih, const float* __restrict__ whh,
           const float* __restrict__ bih, const float* __restrict__ bhh,
           const float* __restrict__ dw0, const float* __restrict__ db0,
           const float* __restrict__ dw1, const float* __restrict__ db1,
           float* __restrict__ out) {
    extern __shared__ float sm[];
    float* xps  = sm + F_XPS;
    float* wihs = sm + F_WIHS;
    float* bihs = sm + F_BIHS;
    float* bhhs = sm + F_BHHS;
    float* dw1s = sm + F_DW1;
    float* db0s = sm + F_DB0;
    uint4* dsm4 = (uint4*)(sm + F_DFRAG);
    char*  t0   = (char*)(sm + F_T0);
    char*  t1   = (char*)(sm + F_T1);
    float* hsm  = sm + F_HS;
    float* ha   = sm + F_HA;

    const int tid  = threadIdx.x;
    const int wid  = tid >> 5;      // 0..7: unit block [wid*16, wid*16+16)
    const int lane = tid & 31;
    const int qrow = lane >> 2;     // 0..7
    const int qcol = lane & 3;      // 0..3
    const int row0 = blockIdx.x * ROWS;

    // ---- small smem init ----
    for (int j = tid; j < 384; j += NTHR) {
        wihs[j] = wih[j]; bihs[j] = bih[j]; bhhs[j] = bhh[j];
    }
    for (int j = tid; j < 256; j += NTHR) dsm4[j] = __ldg(&g_dfrag[j]);
    if (tid < 16) { dw1s[tid] = dw1[tid]; db0s[tid] = db0[tid]; }
    if (tid == 0) sm[F_DB1] = db1[0];
    if (tid < ROWS) {
        xps[tid] = 0.0f;
        out[(u64)(row0 + tid)*50] = 0.0f;
    }

    // ---- encoder (scalar fp32, 256 threads, 32 rows) ----
    {
        const int p = tid & 15, t = tid >> 4;
        float acc[8][2];
        #pragma unroll
        for (int uu = 0; uu < 8; ++uu)
            #pragma unroll
            for (int m = 0; m < 2; ++m) acc[uu][m] = 0.0f;
        const float4* x4  = (const float4*)x;
        const float4* w04 = (const float4*)ew0;
        for (int k4 = 0; k4 < 64; ++k4) {
            float xa[2][4];
            #pragma unroll
            for (int m = 0; m < 2; ++m) {
                float4 v = __ldg(&x4[(u64)(row0 + p + 16*m)*64 + k4]);
                xa[m][0] = v.x; xa[m][1] = v.y; xa[m][2] = v.z; xa[m][3] = v.w;
            }
            #pragma unroll
            for (int kk = 0; kk < 4; ++kk) {
                #pragma unroll
                for (int ub = 0; ub < 2; ++ub) {
                    float4 wv = __ldg(&w04[(k4*4 + kk)*32 + t*2 + ub]);
                    #pragma unroll
                    for (int m = 0; m < 2; ++m) {
                        acc[ub*4+0][m] = fmaf(wv.x, xa[m][kk], acc[ub*4+0][m]);
                        acc[ub*4+1][m] = fmaf(wv.y, xa[m][kk], acc[ub*4+1][m]);
                        acc[ub*4+2][m] = fmaf(wv.z, xa[m][kk], acc[ub*4+2][m]);
                        acc[ub*4+3][m] = fmaf(wv.w, xa[m][kk], acc[ub*4+3][m]);
                    }
                }
            }
        }
        __syncthreads();
        #pragma unroll
        for (int uu = 0; uu < 8; ++uu) {
            int u = t*8 + uu;
            float bv = __ldg(&eb0[u]);
            #pragma unroll
            for (int m = 0; m < 2; ++m)
                ha[(p + 16*m)*HPAD + u] = fmaxf(acc[uu][m] + bv, 0.0f);
        }
        __syncthreads();
        enc_layer128(ew1, eb1, ha, p, tid >> 4, true);
        enc_layer128(ew2, eb2, ha, p, tid >> 4, false);
    }

    // ---- h0: ha -> fp16 tile0 + hold slots ----
    for (int j = tid; j < 4096; j += NTHR) {
        int r = j >> 7, u = j & 127;
        *(__half*)(t0 + r*272 + u*2) = __float2half(ha[r*HPAD + u]);
    }
    #pragma unroll
    for (int nt = 0; nt < 4; ++nt)
        #pragma unroll
        for (int i = 0; i < 2; ++i)
            #pragma unroll
            for (int j = 0; j < 2; ++j) {
                int u = wid*16 + qrow + 8*i;
                int r = nt*8 + qcol*2 + j;
                hsm[(nt*4 + i*2 + j)*NTHR + tid] = ha[r*HPAD + u];
            }
    __syncthreads();

    // ---- register-resident GRU weights (persist across all 49 steps) ----
    uint4 wreg[3][8];
    #pragma unroll
    for (int g = 0; g < 3; ++g)
        #pragma unroll
        for (int k = 0; k < 8; ++k)
            wreg[g][k] = __ldg(&g_wfrag[(g*8 + wid)*256 + k*32 + lane]);

    const float db1v = sm[F_DB1];

    // ---- GRU + decoder, 49 steps ----
    for (int s = 0; s < NSTEP; ++s) {
        const char* tin = (s & 1) ? t1 : t0;
        char* tout      = (s & 1) ? t0 : t1;

        #pragma unroll
        for (int nt = 0; nt < 4; ++nt) {
            float acc[3][4];
            #pragma unroll
            for (int g = 0; g < 3; ++g)
                #pragma unroll
                for (int q = 0; q < 4; ++q) acc[g][q] = 0.0f;

            #pragma unroll
            for (int k = 0; k < 8; ++k) {
                int off = (nt*8 + qrow)*272 + k*32 + qcol*4;
                u32 b0 = *(const u32*)(tin + off);
                u32 b1 = *(const u32*)(tin + off + 16);
                MMA(acc[0], wreg[0][k], b0, b1);
                MMA(acc[1], wreg[1][k], b0, b1);
                MMA(acc[2], wreg[2][k], b0, b1);
            }

            #pragma unroll
            for (int i = 0; i < 2; ++i) {
                int u = wid*16 + qrow + 8*i;
                float wir = wihs[u], wiz = wihs[128 + u], win = wihs[256 + u];
                float br  = bihs[u]       + bhhs[u];
                float bz  = bihs[128 + u] + bhhs[128 + u];
                float bni = bihs[256 + u];
                float bnh = bhhs[256 + u];
                #pragma unroll
                for (int j = 0; j < 2; ++j) {
                    int q = 2*i + j;
                    int r = nt*8 + qcol*2 + j;
                    int slot = (nt*4 + i*2 + j)*NTHR + tid;
                    float xp   = xps[r];
                    float hold = hsm[slot];
                    float rg = sigm(acc[0][q] + fmaf(xp, wir, br));
                    float zg = sigm(acc[1][q] + fmaf(xp, wiz, bz));
                    float ng = tanha(fmaf(xp, win, bni) + rg*(acc[2][q] + bnh));
                    float h  = (1.0f - zg)*ng + zg*hold;
                    hsm[slot] = h;
                    *(__half*)(tout + r*272 + u*2) = __float2half(h);
                }
            }
        }
        __syncthreads();   // h_{s+1} tile complete

        // ---- decoder on tout (warps 0..3, 8 rows each) -> out col s+1, xps ----
        if (wid < 4) {
            float dacc[4] = {0.0f, 0.0f, 0.0f, 0.0f};
            #pragma unroll
            for (int k = 0; k < 8; ++k) {
                int off = (wid*8 + qrow)*272 + k*32 + qcol*4;
                u32 b0 = *(const u32*)(tout + off);
                u32 b1 = *(const u32*)(tout + off + 16);
                uint4 ah = dsm4[k*32 + lane];
                MMA(dacc, ah, b0, b1);
            }
            int i = qrow;
            float w1a = dw1s[i], w1b = dw1s[i + 8];
            float b0a = db0s[i], b0b = db0s[i + 8];
            float v0 = fmaxf(dacc[0] + b0a, 0.0f)*w1a + fmaxf(dacc[2] + b0b, 0.0f)*w1b;
            float v1 = fmaxf(dacc[1] + b0a, 0.0f)*w1a + fmaxf(dacc[3] + b0b, 0.0f)*w1b;
            v0 += __shfl_xor_sync(0xffffffffu, v0, 4);
            v0 += __shfl_xor_sync(0xffffffffu, v0, 8);
            v0 += __shfl_xor_sync(0xffffffffu, v0, 16);
            v1 += __shfl_xor_sync(0xffffffffu, v1, 4);
            v1 += __shfl_xor_sync(0xffffffffu, v1, 8);
            v1 += __shfl_xor_sync(0xffffffffu, v1, 16);
            if (lane < 4) {
                int r0 = wid*8 + lane*2;
                float o0 = v0 + db1v;
                float o1 = v1 + db1v;
                out[(u64)(row0 + r0)*50 + s + 1] = o0;
                out[(u64)(row0 + r0 + 1)*50 + s + 1] = o1;
                xps[r0]     = o0;
                xps[r0 + 1] = o1;
            }
        }
        __syncthreads();   // xps ready for next step
    }
}

extern "C" void kernel_launch(void* const* d_in, const int* in_sizes, int n_in,
                              void* d_out, int out_size) {
    (void)in_sizes; (void)n_in; (void)out_size;
    const float* x   = (const float*)d_in[0];
    const float* ew0 = (const float*)d_in[1];
    const float* eb0 = (const float*)d_in[2];
    const float* ew1 = (const float*)d_in[3];
    const float* eb1 = (const float*)d_in[4];
    const float* ew2 = (const float*)d_in[5];
    const float* eb2 = (const float*)d_in[6];
    const float* wih = (const float*)d_in[7];
    const float* whh = (const float*)d_in[8];
    const float* bih = (const float*)d_in[9];
    const float* bhh = (const float*)d_in[10];
    const float* dw0 = (const float*)d_in[11];
    const float* db0 = (const float*)d_in[12];
    const float* dw1 = (const float*)d_in[13];
    const float* db1 = (const float*)d_in[14];
    float* out = (float*)d_out;

    cudaFuncSetAttribute(gru_kernel, cudaFuncAttributeMaxDynamicSharedMemorySize, SMEM_BYTES);

    repack<<<13, 512>>>(whh, dw0);
    gru_kernel<<<NBLK, NTHR, SMEM_BYTES>>>(x, ew0, eb0, ew1, eb1, ew2, eb2,
                                           wih, whh, bih, bhh, dw0, db0, dw1, db1, out);
}

// round 17
// speedup vs baseline: 1.1540x; 1.0574x over previous
#include <cuda_runtime.h>
#include <cuda_fp16.h>

typedef unsigned int u32;
typedef unsigned long long u64;

#define NBLK  256
#define NTHR  256
#define ROWS  32
#define HPAD  132
#define NSTEP 49
#define TS    288   // tile row stride bytes (72 words: conflict-free LDS.64)

// ---- dynamic smem layout (float offsets) ----
#define F_XPS   0        // 32
#define F_GP4   32       // 128 float4 = 512 (wir, wiz, win, bnh)
#define F_GB4   544      // 512 (br, bz, bni, 0)
#define F_DW1   1056     // 16
#define F_DB0   1072     // 16
#define F_DB1   1088     // 1 (pad to 1152)
#define F_DFRAG 1152     // 256 uint4 = 1024
#define F_T0    2176     // fp16 tile 32*72 floats = 2304
#define F_T1    4480     // 2304
#define F_HS    6784     // 16*256 = 4096
#define F_HA    10880    // encoder scratch 32*132 = 4224
#define SMEM_FLOATS 15104
#define SMEM_BYTES  (SMEM_FLOATS*4)

// GRU A fragments (fp16, (k,k+8)-paired): [g][wm][k][lane] uint4
__device__ uint4 g_wfrag[3 * 8 * 8 * 32];
// decoder A fragments: [k][lane] uint4
__device__ uint4 g_dfrag[8 * 32];

#define MMA(c, a, b0v, b1v) asm volatile( \
    "mma.sync.aligned.m16n8k16.row.col.f32.f16.f16.f32 " \
    "{%0,%1,%2,%3}, {%4,%5,%6,%7}, {%8,%9}, {%0,%1,%2,%3};" \
    : "+f"((c)[0]), "+f"((c)[1]), "+f"((c)[2]), "+f"((c)[3]) \
    : "r"((a).x), "r"((a).y), "r"((a).z), "r"((a).w), "r"(b0v), "r"(b1v))

__device__ __forceinline__ float tanha(float x) {
    float y;
    asm("tanh.approx.f32 %0, %1;" : "=f"(y) : "f"(x));
    return y;
}
__device__ __forceinline__ float sigm(float x) {
    return fmaf(0.5f, tanha(0.5f * x), 0.5f);
}
__device__ __forceinline__ u32 pack_h2(__half lo, __half hi) {
    return ((u32)__half_as_ushort(hi) << 16) | (u32)__half_as_ushort(lo);
}
// pack two f32 -> f16x2: lo half = a, hi half = b
__device__ __forceinline__ u32 cvt_h2(float a, float b) {
    u32 r;
    asm("cvt.rn.f16x2.f32 %0, %1, %2;" : "=r"(r) : "f"(b), "f"(a));
    return r;
}
// sigma: slot of unit u within tile (interleaved m / m+8)
__device__ __forceinline__ int sigma_u(int u) {
    int w = u & 15;
    return (u & ~15) + 2*(w & 7) + (w >> 3);
}

// ---------------- weight repack (fp16, (k, k+8) pairing) ----------------
__global__ void repack(const float* __restrict__ whh, const float* __restrict__ dw0) {
    int idx = blockIdx.x * blockDim.x + threadIdx.x;
    if (idx < 6144) {
        int lane = idx & 31;
        int k    = (idx >> 5) & 7;
        int wm   = (idx >> 8) & 7;
        int g    = idx >> 11;          // 0..2
        int row  = g * 128 + wm * 16 + (lane >> 2);
        int k0   = k * 16 + (lane & 3) * 2;
        u32 o[4];
        #pragma unroll
        for (int q = 0; q < 4; ++q) {
            int rr = row + 8 * (q & 1);
            int kk = k0 + (q >> 1);
            o[q] = pack_h2(__float2half(whh[rr * 128 + kk]),
                           __float2half(whh[rr * 128 + kk + 8]));
        }
        g_wfrag[idx] = make_uint4(o[0], o[1], o[2], o[3]);
    } else if (idx < 6400) {
        int local = idx - 6144;
        int lane = local & 31;
        int k    = local >> 5;         // 0..7
        int row  = lane >> 2;
        int k0   = k * 16 + (lane & 3) * 2;
        u32 o[4];
        #pragma unroll
        for (int q = 0; q < 4; ++q) {
            int rr = row + 8 * (q & 1);
            int kk = k0 + (q >> 1);
            o[q] = pack_h2(__float2half(dw0[kk * 16 + rr]),
                           __float2half(dw0[(kk + 8) * 16 + rr]));
        }
        g_dfrag[local] = make_uint4(o[0], o[1], o[2], o[3]);
    }
}

// one 128->128 encoder layer (reads/writes ha), scalar fp32, 256 threads, 32 rows
__device__ __forceinline__ void enc_layer128(const float* __restrict__ w,
                                             const float* __restrict__ b,
                                             float* ha, int p, int t, bool relu_on) {
    float acc[8][2];
    #pragma unroll
    for (int uu = 0; uu < 8; ++uu)
        #pragma unroll
        for (int m = 0; m < 2; ++m) acc[uu][m] = 0.0f;
    const float4* w4 = (const float4*)w;
    for (int k4 = 0; k4 < 32; ++k4) {
        float xa[2][4];
        #pragma unroll
        for (int m = 0; m < 2; ++m) {
            float4 v = *(const float4*)&ha[(p + 16*m)*HPAD + k4*4];
            xa[m][0] = v.x; xa[m][1] = v.y; xa[m][2] = v.z; xa[m][3] = v.w;
        }
        #pragma unroll
        for (int kk = 0; kk < 4; ++kk) {
            #pragma unroll
            for (int ub = 0; ub < 2; ++ub) {
                float4 wv = __ldg(&w4[(k4*4 + kk)*32 + t*2 + ub]);
                #pragma unroll
                for (int m = 0; m < 2; ++m) {
                    acc[ub*4+0][m] = fmaf(wv.x, xa[m][kk], acc[ub*4+0][m]);
                    acc[ub*4+1][m] = fmaf(wv.y, xa[m][kk], acc[ub*4+1][m]);
                    acc[ub*4+2][m] = fmaf(wv.z, xa[m][kk], acc[ub*4+2][m]);
                    acc[ub*4+3][m] = fmaf(wv.w, xa[m][kk], acc[ub*4+3][m]);
                }
            }
        }
    }
    __syncthreads();
    #pragma unroll
    for (int uu = 0; uu < 8; ++uu) {
        int u = t*8 + uu;
        float bv = __ldg(&b[u]);
        #pragma unroll
        for (int m = 0; m < 2; ++m) {
            float v = acc[uu][m] + bv;
            ha[(p + 16*m)*HPAD + u] = relu_on ? fmaxf(v, 0.0f) : v;
        }
    }
    __syncthreads();
}

__global__ void __launch_bounds__(NTHR, 2)
gru_kernel(const float* __restrict__ x,
           const float* __restrict__ ew0, const float* __restrict__ eb0,
           const float* __restrict__ ew1, const float* __restrict__ eb1,
           const float* __restrict__ ew2, const float* __restrict__ eb2,
           const float* __restrict__ wih, const float* __restrict__ whh,
           const float* __restrict__ bih, const float* __restrict__ bhh,
           const float* __restrict__ dw0, const float* __restrict__ db0,
           const float* __restrict__ dw1, const float* __restrict__ db1,
           float* __restrict__ out) {
    extern __shared__ float sm[];
    float*  xps  = sm + F_XPS;
    float4* gp4  = (float4*)(sm + F_GP4);
    float4* gb4  = (float4*)(sm + F_GB4);
    float*  dw1s = sm + F_DW1;
    float*  db0s = sm + F_DB0;
    uint4*  dsm4 = (uint4*)(sm + F_DFRAG);
    char*   t0   = (char*)(sm + F_T0);
    char*   t1   = (char*)(sm + F_T1);
    float*  hsm  = sm + F_HS;
    float*  ha   = sm + F_HA;

    const int tid  = threadIdx.x;
    const int wid  = tid >> 5;      // 0..7: unit block [wid*16, wid*16+16)
    const int lane = tid & 31;
    const int qrow = lane >> 2;     // 0..7
    const int qcol = lane & 3;      // 0..3
    const int row0 = blockIdx.x * ROWS;

    // ---- small smem init ----
    for (int j = tid; j < 128; j += NTHR) {
        gp4[j] = make_float4(wih[j], wih[128 + j], wih[256 + j], bhh[256 + j]);
        gb4[j] = make_float4(bih[j] + bhh[j], bih[128 + j] + bhh[128 + j], bih[256 + j], 0.0f);
    }
    for (int j = tid; j < 256; j += NTHR) dsm4[j] = __ldg(&g_dfrag[j]);
    if (tid < 16) { dw1s[tid] = dw1[tid]; db0s[tid] = db0[tid]; }
    if (tid == 0) sm[F_DB1] = db1[0];
    if (tid < ROWS) {
        xps[tid] = 0.0f;
        out[(u64)(row0 + tid)*50] = 0.0f;
    }

    // ---- encoder (scalar fp32, 256 threads, 32 rows) ----
    {
        const int p = tid & 15, t = tid >> 4;
        float acc[8][2];
        #pragma unroll
        for (int uu = 0; uu < 8; ++uu)
            #pragma unroll
            for (int m = 0; m < 2; ++m) acc[uu][m] = 0.0f;
        const float4* x4  = (const float4*)x;
        const float4* w04 = (const float4*)ew0;
        for (int k4 = 0; k4 < 64; ++k4) {
            float xa[2][4];
            #pragma unroll
            for (int m = 0; m < 2; ++m) {
                float4 v = __ldg(&x4[(u64)(row0 + p + 16*m)*64 + k4]);
                xa[m][0] = v.x; xa[m][1] = v.y; xa[m][2] = v.z; xa[m][3] = v.w;
            }
            #pragma unroll
            for (int kk = 0; kk < 4; ++kk) {
                #pragma unroll
                for (int ub = 0; ub < 2; ++ub) {
                    float4 wv = __ldg(&w04[(k4*4 + kk)*32 + t*2 + ub]);
                    #pragma unroll
                    for (int m = 0; m < 2; ++m) {
                        acc[ub*4+0][m] = fmaf(wv.x, xa[m][kk], acc[ub*4+0][m]);
                        acc[ub*4+1][m] = fmaf(wv.y, xa[m][kk], acc[ub*4+1][m]);
                        acc[ub*4+2][m] = fmaf(wv.z, xa[m][kk], acc[ub*4+2][m]);
                        acc[ub*4+3][m] = fmaf(wv.w, xa[m][kk], acc[ub*4+3][m]);
                    }
                }
            }
        }
        __syncthreads();
        #pragma unroll
        for (int uu = 0; uu < 8; ++uu) {
            int u = t*8 + uu;
            float bv = __ldg(&eb0[u]);
            #pragma unroll
            for (int m = 0; m < 2; ++m)
                ha[(p + 16*m)*HPAD + u] = fmaxf(acc[uu][m] + bv, 0.0f);
        }
        __syncthreads();
        enc_layer128(ew1, eb1, ha, p, tid >> 4, true);
        enc_layer128(ew2, eb2, ha, p, tid >> 4, false);
    }

    // ---- h0: ha -> sigma-permuted fp16 tile0 + hold slots ----
    for (int j = tid; j < 4096; j += NTHR) {
        int r = j >> 7, u = j & 127;
        *(__half*)(t0 + r*TS + sigma_u(u)*2) = __float2half(ha[r*HPAD + u]);
    }
    #pragma unroll
    for (int nt = 0; nt < 4; ++nt)
        #pragma unroll
        for (int i = 0; i < 2; ++i)
            #pragma unroll
            for (int j = 0; j < 2; ++j) {
                int u = wid*16 + qrow + 8*i;
                int r = nt*8 + qcol*2 + j;
                hsm[(nt*4 + i*2 + j)*NTHR + tid] = ha[r*HPAD + u];
            }
    __syncthreads();

    // ---- register-resident GRU weights ----
    uint4 wreg[3][8];
    #pragma unroll
    for (int g = 0; g < 3; ++g)
        #pragma unroll
        for (int k = 0; k < 8; ++k)
            wreg[g][k] = __ldg(&g_wfrag[(g*8 + wid)*256 + k*32 + lane]);

    const float db1v = sm[F_DB1];
    const int u0 = wid*16 + qrow;

    // ---- GRU + decoder, 49 steps ----
    for (int s = 0; s < NSTEP; ++s) {
        const char* tin = (s & 1) ? t1 : t0;
        char* tout      = (s & 1) ? t0 : t1;

        #pragma unroll
        for (int nt = 0; nt < 4; ++nt) {
            float acc[3][4];
            #pragma unroll
            for (int g = 0; g < 3; ++g)
                #pragma unroll
                for (int q = 0; q < 4; ++q) acc[g][q] = 0.0f;

            #pragma unroll
            for (int k = 0; k < 8; ++k) {
                uint2 bb = *(const uint2*)(tin + (nt*8 + qrow)*TS + k*32 + qcol*8);
                MMA(acc[0], wreg[0][k], bb.x, bb.y);
                MMA(acc[1], wreg[1][k], bb.x, bb.y);
                MMA(acc[2], wreg[2][k], bb.x, bb.y);
            }

            float4 P0 = gp4[u0],     Q0 = gb4[u0];
            float4 P1 = gp4[u0 + 8], Q1 = gb4[u0 + 8];
            #pragma unroll
            for (int j = 0; j < 2; ++j) {
                int r = nt*8 + qcol*2 + j;
                float xp = xps[r];
                // i = 0 (unit u0), q = j
                int s0 = (nt*4 + j)*NTHR + tid;
                float hold0 = hsm[s0];
                float rg0 = sigm(acc[0][j] + fmaf(xp, P0.x, Q0.x));
                float zg0 = sigm(acc[1][j] + fmaf(xp, P0.y, Q0.y));
                float ng0 = tanha(fmaf(xp, P0.z, Q0.z) + rg0*(acc[2][j] + P0.w));
                float h0v = (1.0f - zg0)*ng0 + zg0*hold0;
                hsm[s0] = h0v;
                // i = 1 (unit u0+8), q = 2+j
                int s1 = (nt*4 + 2 + j)*NTHR + tid;
                float hold1 = hsm[s1];
                float rg1 = sigm(acc[0][2+j] + fmaf(xp, P1.x, Q1.x));
                float zg1 = sigm(acc[1][2+j] + fmaf(xp, P1.y, Q1.y));
                float ng1 = tanha(fmaf(xp, P1.z, Q1.z) + rg1*(acc[2][2+j] + P1.w));
                float h1v = (1.0f - zg1)*ng1 + zg1*hold1;
                hsm[s1] = h1v;
                // adjacent sigma slots -> one STS.32
                *(u32*)(tout + r*TS + wid*32 + qrow*4) = cvt_h2(h0v, h1v);
            }
        }
        __syncthreads();   // h_{s+1} tile complete

        // ---- decoder on tout (warps 0..3, 8 rows each) ----
        if (wid < 4) {
            float dacc[4] = {0.0f, 0.0f, 0.0f, 0.0f};
            #pragma unroll
            for (int k = 0; k < 8; ++k) {
                uint2 bb = *(const uint2*)(tout + (wid*8 + qrow)*TS + k*32 + qcol*8);
                uint4 ah = dsm4[k*32 + lane];
                MMA(dacc, ah, bb.x, bb.y);
            }
            int i = qrow;
            float w1a = dw1s[i], w1b = dw1s[i + 8];
            float b0a = db0s[i], b0b = db0s[i + 8];
            float v0 = fmaxf(dacc[0] + b0a, 0.0f)*w1a + fmaxf(dacc[2] + b0b, 0.0f)*w1b;
            float v1 = fmaxf(dacc[1] + b0a, 0.0f)*w1a + fmaxf(dacc[3] + b0b, 0.0f)*w1b;
            v0 += __shfl_xor_sync(0xffffffffu, v0, 4);
            v0 += __shfl_xor_sync(0xffffffffu, v0, 8);
            v0 += __shfl_xor_sync(0xffffffffu, v0, 16);
            v1 += __shfl_xor_sync(0xffffffffu, v1, 4);
            v1 += __shfl_xor_sync(0xffffffffu, v1, 8);
            v1 += __shfl_xor_sync(0xffffffffu, v1, 16);
            if (lane < 4) {
                int r0 = wid*8 + lane*2;
                float o0 = v0 + db1v;
                float o1 = v1 + db1v;
                out[(u64)(row0 + r0)*50 + s + 1] = o0;
                out[(u64)(row0 + r0 + 1)*50 + s + 1] = o1;
                xps[r0]     = o0;
                xps[r0 + 1] = o1;
            }
        }
        __syncthreads();   // xps ready for next step
    }
}

extern "C" void kernel_launch(void* const* d_in, const int* in_sizes, int n_in,
                              void* d_out, int out_size) {
    (void)in_sizes; (void)n_in; (void)out_size;
    const float* x   = (const float*)d_in[0];
    const float* ew0 = (const float*)d_in[1];
    const float* eb0 = (const float*)d_in[2];
    const float* ew1 = (const float*)d_in[3];
    const float* eb1 = (const float*)d_in[4];
    const float* ew2 = (const float*)d_in[5];
    const float* eb2 = (const float*)d_in[6];
    const float* wih = (const float*)d_in[7];
    const float* whh = (const float*)d_in[8];
    const float* bih = (const float*)d_in[9];
    const float* bhh = (const float*)d_in[10];
    const float* dw0 = (const float*)d_in[11];
    const float* db0 = (const float*)d_in[12];
    const float* dw1 = (const float*)d_in[13];
    const float* db1 = (const float*)d_in[14];
    float* out = (float*)d_out;

    cudaFuncSetAttribute(gru_kernel, cudaFuncAttributeMaxDynamicSharedMemorySize, SMEM_BYTES);

    repack<<<13, 512>>>(whh, dw0);
    gru_kernel<<<NBLK, NTHR, SMEM_BYTES>>>(x, ew0, eb0, ew1, eb1, ew2, eb2,
                                           wih, whh, bih, bhh, dw0, db0, dw1, db1, out);
}